// round 4
// baseline (speedup 1.0000x reference)
#include <cuda_runtime.h>

#define TOKENS  65536
#define KCODES  1024
#define DDIM    64
#define HW      4096
#define TM      128
#define TN      64
#define SROW    68          // floats; 272B rows: 16B-aligned, conflict-free LDS.128

typedef unsigned long long ull;

__device__ float g_hn[KCODES];

// Kernel 0: half squared norms, one warp per codebook row
__global__ void vq_norms(const float* __restrict__ cb) {
    int w    = (blockIdx.x * blockDim.x + threadIdx.x) >> 5;
    int lane = threadIdx.x & 31;
    if (w < KCODES) {
        float v0 = cb[w * DDIM + lane];
        float v1 = cb[w * DDIM + 32 + lane];
        float s = v0 * v0 + v1 * v1;
        #pragma unroll
        for (int m = 16; m >= 1; m >>= 1) s += __shfl_xor_sync(0xffffffffu, s, m);
        if (lane == 0) g_hn[w] = 0.5f * s;
    }
}

// Kernel 1: argmax(x.c - 0.5*|c|^2), K-pair f32x2 accumulation.
// 128 tokens x 64-code chunks; 256 threads as 32 token-rows x 8 code-cols;
// 4 tokens x 8 codes per thread. b staged as 128-bit loads (k-quads).
__global__ __launch_bounds__(256, 2)
void vq_main(const float* __restrict__ inp, const float* __restrict__ cb,
             float* __restrict__ out, int out_size) {
    extern __shared__ float smem[];
    float* sx   = smem;                  // [128][SROW]  token tile [t][d]
    float* sc   = sx + TM * SROW;        // [64][SROW]   code tile  [c][d]
    float* shn  = sc + TN * SROW;        // [64]
    int*   sidx = (int*)(shn + TN);      // [128]

    int tid = threadIdx.x;
    int tx = tid & 7;                    // code column (8)
    int ty = tid >> 3;                   // token row   (32)
    int n0 = blockIdx.x * TM;
    int b  = n0 >> 12, s0 = n0 & (HW - 1);
    const float* ibase = inp + (long long)b * DDIM * HW + s0;

    for (int e = tid; e < TM * DDIM; e += 256) {
        int d = e >> 7, t = e & 127;
        sx[t * SROW + d] = ibase[d * HW + t];
    }

    float bestv[4]; int besti[4];
    #pragma unroll
    for (int i = 0; i < 4; ++i) { bestv[i] = -3.4e38f; besti[i] = 0; }

    const float* axb = sx + ty * SROW;   // token t = ty + 32p
    const float* bxb = sc + tx * SROW;   // code  c = tx + 8q

    for (int c0 = 0; c0 < KCODES; c0 += TN) {
        __syncthreads();
        for (int e = tid; e < TN * DDIM; e += 256) {
            int c = e >> 6, k = e & 63;
            sc[c * SROW + k] = cb[(c0 + c) * DDIM + k];
        }
        if (tid < TN) shn[tid] = g_hn[c0 + tid];
        __syncthreads();

        ull acc[4][8];
        #pragma unroll
        for (int p = 0; p < 4; ++p)
            #pragma unroll
            for (int q = 0; q < 8; ++q) acc[p][q] = 0ull;

        // k-quad mainloop: 4 d-values per iteration.
        // b: 8 LDS.128 (ull2), a: 8 LDS.64, then 64 FFMA2.
        #pragma unroll 4
        for (int k4 = 0; k4 < DDIM / 4; ++k4) {
            ull b0[8], b1[8];
            #pragma unroll
            for (int q = 0; q < 8; ++q) {
                ulonglong2 bv = *(const ulonglong2*)(bxb + q * 8 * SROW + 4 * k4);
                b0[q] = bv.x; b1[q] = bv.y;
            }
            #pragma unroll
            for (int p = 0; p < 4; ++p) {
                ull a0 = *(const ull*)(axb + p * 32 * SROW + 4 * k4);
                ull a1 = *(const ull*)(axb + p * 32 * SROW + 4 * k4 + 2);
                #pragma unroll
                for (int q = 0; q < 8; ++q)
                    asm("fma.rn.f32x2 %0, %1, %2, %0;"
                        : "+l"(acc[p][q]) : "l"(a0), "l"(b0[q]));
                #pragma unroll
                for (int q = 0; q < 8; ++q)
                    asm("fma.rn.f32x2 %0, %1, %2, %0;"
                        : "+l"(acc[p][q]) : "l"(a1), "l"(b1[q]));
            }
        }

        // Chunk epilogue: per-thread codes ascend with q; chunks ascend;
        // strict > keeps lowest index on ties.
        #pragma unroll
        for (int q = 0; q < 8; ++q) {
            float hn = shn[tx + 8 * q];
            int cg = c0 + tx + 8 * q;
            #pragma unroll
            for (int p = 0; p < 4; ++p) {
                float lo, hi;
                asm("mov.b64 {%0, %1}, %2;" : "=f"(lo), "=f"(hi) : "l"(acc[p][q]));
                float v = (lo + hi) - hn;
                if (v > bestv[p]) { bestv[p] = v; besti[p] = cg; }
            }
        }
    }

    // Reduce across the 8 code-columns (tx = lane&7): xor masks 4,2,1.
    #pragma unroll
    for (int p = 0; p < 4; ++p) {
        float v = bestv[p]; int ix = besti[p];
        #pragma unroll
        for (int m = 4; m >= 1; m >>= 1) {
            float ov = __shfl_xor_sync(0xffffffffu, v,  m);
            int   oi = __shfl_xor_sync(0xffffffffu, ix, m);
            if (ov > v || (ov == v && oi < ix)) { v = ov; ix = oi; }
        }
        if (tx == 0) sidx[ty + 32 * p] = ix;
    }
    __syncthreads();

    // Fused gather: writes coalesced over t; codebook reads hit L2.
    for (int e = tid; e < TM * DDIM; e += 256) {
        int d = e >> 7, t = e & 127;
        out[((long long)b * DDIM + d) * HW + s0 + t] = cb[sidx[t] * DDIM + d];
    }
    if (out_size > TOKENS * DDIM && tid < TM)
        out[TOKENS * DDIM + n0 + tid] = (float)sidx[tid];
}

#define SMEM_BYTES (((TM + TN) * SROW + TN) * 4 + TM * 4)

extern "C" void kernel_launch(void* const* d_in, const int* in_sizes, int n_in,
                              void* d_out, int out_size) {
    const float* inp = (const float*)d_in[0];   // (16, 64, 64, 64) f32
    const float* cb  = (const float*)d_in[1];   // (1024, 64) f32
    float* out = (float*)d_out;

    cudaFuncSetAttribute(vq_main, cudaFuncAttributeMaxDynamicSharedMemorySize,
                         SMEM_BYTES);

    vq_norms<<<KCODES * 32 / 256, 256>>>(cb);
    vq_main<<<TOKENS / TM, 256, SMEM_BYTES>>>(inp, cb, out, out_size);
}

// round 5
// speedup vs baseline: 1.0075x; 1.0075x over previous
#include <cuda_runtime.h>

#define TOKENS  65536
#define KCODES  1024
#define DDIM    64
#define HW      4096
#define TM      64
#define TN      64
#define SROW    66          // floats; 264B rows -> 8B aligned, conflict-free LDS.64

typedef unsigned long long ull;

__device__ float g_hn[KCODES];

// Kernel 0: half squared norms, one warp per codebook row
__global__ void vq_norms(const float* __restrict__ cb) {
    int w    = (blockIdx.x * blockDim.x + threadIdx.x) >> 5;
    int lane = threadIdx.x & 31;
    if (w < KCODES) {
        float v0 = cb[w * DDIM + lane];
        float v1 = cb[w * DDIM + 32 + lane];
        float s = v0 * v0 + v1 * v1;
        #pragma unroll
        for (int m = 16; m >= 1; m >>= 1) s += __shfl_xor_sync(0xffffffffu, s, m);
        if (lane == 0) g_hn[w] = 0.5f * s;
    }
}

// Kernel 1: argmax(x.c - 0.5*|c|^2), K-pair f32x2 accumulation.
// 64-token x 64-code tile, 256 threads as 16x16, 4 tokens x 4 codes/thread.
// Small acc footprint (16 ull) -> 3 CTAs/SM for latency hiding.
__global__ __launch_bounds__(256, 3)
void vq_main(const float* __restrict__ inp, const float* __restrict__ cb,
             float* __restrict__ out, int out_size) {
    extern __shared__ float smem[];
    float* sx   = smem;                  // [64][SROW] token tile [t][d]
    float* sc   = sx + TM * SROW;        // [64][SROW] code tile  [c][d]
    float* shn  = sc + TN * SROW;        // [64]
    int*   sidx = (int*)(shn + TN);      // [64]

    int tid = threadIdx.x;
    int tx = tid & 15;                   // code column (16)
    int ty = tid >> 4;                   // token row   (16)
    int n0 = blockIdx.x * TM;            // 64 consecutive tokens, same batch b
    int b  = n0 >> 12, s0 = n0 & (HW - 1);
    const float* ibase = inp + (long long)b * DDIM * HW + s0;

    // x[t][d] = ibase[d*HW + t]; gmem coalesced over t (64 floats/row)
    for (int e = tid; e < TM * DDIM; e += 256) {
        int d = e >> 6, t = e & 63;
        sx[t * SROW + d] = ibase[d * HW + t];
    }

    float bestv[4]; int besti[4];
    #pragma unroll
    for (int i = 0; i < 4; ++i) { bestv[i] = -3.4e38f; besti[i] = 0; }

    const float* axb = sx + ty * SROW;   // token t = ty + 16p (broadcast loads)
    const float* bxb = sc + tx * SROW;   // code  c = tx + 16q (banks 2*tx: distinct)

    for (int c0 = 0; c0 < KCODES; c0 += TN) {
        __syncthreads();
        for (int e = tid; e < TN * DDIM; e += 256) {
            int c = e >> 6, k = e & 63;
            sc[c * SROW + k] = cb[(c0 + c) * DDIM + k];
        }
        if (tid < TN) shn[tid] = g_hn[c0 + tid];
        __syncthreads();

        ull acc[4][4];
        #pragma unroll
        for (int p = 0; p < 4; ++p)
            #pragma unroll
            for (int q = 0; q < 4; ++q) acc[p][q] = 0ull;

        // K-pair mainloop: acc.lo = even k, acc.hi = odd k. 8 LDS.64 + 16 FMA2 per k2.
        #pragma unroll 4
        for (int k2 = 0; k2 < DDIM / 2; ++k2) {
            ull a[4], bb[4];
            #pragma unroll
            for (int p = 0; p < 4; ++p)
                a[p] = *(const ull*)(axb + p * 16 * SROW + 2 * k2);
            #pragma unroll
            for (int q = 0; q < 4; ++q)
                bb[q] = *(const ull*)(bxb + q * 16 * SROW + 2 * k2);
            #pragma unroll
            for (int p = 0; p < 4; ++p)
                #pragma unroll
                for (int q = 0; q < 4; ++q)
                    asm("fma.rn.f32x2 %0, %1, %2, %0;"
                        : "+l"(acc[p][q]) : "l"(a[p]), "l"(bb[q]));
        }

        // Chunk epilogue: strict > keeps lowest index on ties (c ascends with q, c0)
        #pragma unroll
        for (int q = 0; q < 4; ++q) {
            float hn = shn[tx + 16 * q];
            int cg = c0 + tx + 16 * q;
            #pragma unroll
            for (int p = 0; p < 4; ++p) {
                float lo, hi;
                asm("mov.b64 {%0, %1}, %2;" : "=f"(lo), "=f"(hi) : "l"(acc[p][q]));
                float v = (lo + hi) - hn;
                if (v > bestv[p]) { bestv[p] = v; besti[p] = cg; }
            }
        }
    }

    // Reduce across the 16 code-columns; lane = (ty&1)*16 + tx, masks stay in tx group.
    #pragma unroll
    for (int p = 0; p < 4; ++p) {
        float v = bestv[p]; int ix = besti[p];
        #pragma unroll
        for (int m = 8; m >= 1; m >>= 1) {
            float ov = __shfl_xor_sync(0xffffffffu, v,  m);
            int   oi = __shfl_xor_sync(0xffffffffu, ix, m);
            if (ov > v || (ov == v && oi < ix)) { v = ov; ix = oi; }
        }
        if (tx == 0) sidx[ty + 16 * p] = ix;
    }
    __syncthreads();

    // Fused gather: out[b][d][s0+t] = cb[idx[t]][d]; coalesced writes, L2-hot reads.
    for (int e = tid; e < TM * DDIM; e += 256) {
        int d = e >> 6, t = e & 63;
        out[((long long)b * DDIM + d) * HW + s0 + t] = cb[sidx[t] * DDIM + d];
    }
    if (out_size > TOKENS * DDIM && tid < TM)
        out[TOKENS * DDIM + n0 + tid] = (float)sidx[tid];
}

#define SMEM_BYTES (((TM + TN) * SROW + TN) * 4 + TM * 4)

extern "C" void kernel_launch(void* const* d_in, const int* in_sizes, int n_in,
                              void* d_out, int out_size) {
    const float* inp = (const float*)d_in[0];   // (16, 64, 64, 64) f32
    const float* cb  = (const float*)d_in[1];   // (1024, 64) f32
    float* out = (float*)d_out;

    cudaFuncSetAttribute(vq_main, cudaFuncAttributeMaxDynamicSharedMemorySize,
                         SMEM_BYTES);

    vq_norms<<<KCODES * 32 / 256, 256>>>(cb);
    vq_main<<<TOKENS / TM, 256, SMEM_BYTES>>>(inp, cb, out, out_size);
}

// round 6
// speedup vs baseline: 1.1383x; 1.1298x over previous
#include <cuda_runtime.h>

#define TOKENS  65536
#define KCODES  1024
#define DDIM    64
#define HW      4096
#define TM      128
#define TN      128
#define SX      130         // transposed row stride (floats): even (8B-aligned LDS.64)

typedef unsigned long long ull;

__device__ float g_hn[KCODES];

// Kernel 0: half squared norms, one warp per codebook row
__global__ void vq_norms(const float* __restrict__ cb) {
    int w    = (blockIdx.x * blockDim.x + threadIdx.x) >> 5;
    int lane = threadIdx.x & 31;
    if (w < KCODES) {
        float v0 = cb[w * DDIM + lane];
        float v1 = cb[w * DDIM + 32 + lane];
        float s = v0 * v0 + v1 * v1;
        #pragma unroll
        for (int m = 16; m >= 1; m >>= 1) s += __shfl_xor_sync(0xffffffffu, s, m);
        if (lane == 0) g_hn[w] = 0.5f * s;
    }
}

// Kernel 1: argmax(x.c - 0.5*|c|^2). Transposed smem tiles [d][token]/[d][code],
// N-packed f32x2 (acc.lo/hi = adjacent codes). 128x128 tile, 16x16 threads,
// 8 tokens x 8 codes (4 code-pairs) per thread. Balanced: 16 crossbar-cyc ==
// 16 SM-FMA-cyc per k-step.
__global__ __launch_bounds__(256, 2)
void vq_main(const float* __restrict__ inp, const float* __restrict__ cb,
             float* __restrict__ out, int out_size) {
    extern __shared__ float smem[];
    float* sxT  = smem;                  // [64][SX]  x^T: [d][t]
    float* scT  = sxT + DDIM * SX;       // [64][SX]  c^T: [d][c]
    float* shn  = scT + DDIM * SX;       // [128]
    int*   sidx = (int*)(shn + TN);      // [128]

    int tid = threadIdx.x;
    int tx = tid & 15;                   // code-pair column (16)
    int ty = tid >> 4;                   // token row        (16)
    int n0 = blockIdx.x * TM;
    int b  = n0 >> 12, s0 = n0 & (HW - 1);
    const float* ibase = inp + (long long)b * DDIM * HW + s0;

    // Fill x^T: sxT[d][t] = ibase[d*HW + t]; gmem coalesced, smem stores conflict-free.
    for (int e = tid; e < TM * DDIM; e += 256) {
        int d = e >> 7, t = e & 127;
        sxT[d * SX + t] = ibase[d * HW + t];
    }

    float bestv[8]; int besti[8];
    #pragma unroll
    for (int i = 0; i < 8; ++i) { bestv[i] = -3.4e38f; besti[i] = 0; }

    const float* axb = sxT + ty;             // token t = ty + 16p
    const float* bxb = scT + 2 * tx;         // codes (2(tx+16q), +1)

    for (int c0 = 0; c0 < KCODES; c0 += TN) {
        __syncthreads();
        // Fill c^T: read cb coalesced (e = c*64+d), store transposed.
        for (int e = tid; e < TN * DDIM; e += 256) {
            int c = e >> 6, d = e & 63;
            scT[d * SX + c] = cb[(c0 + c) * DDIM + d];
        }
        if (tid < TN) shn[tid] = g_hn[c0 + tid];
        __syncthreads();

        ull acc[8][4];
        #pragma unroll
        for (int p = 0; p < 8; ++p)
            #pragma unroll
            for (int q = 0; q < 4; ++q) acc[p][q] = 0ull;

        // Mainloop: per k, 8 broadcast LDS.32 (+dup mov) for tokens,
        // 4 conflict-free LDS.64 for code-pairs, 32 FFMA2.
        #pragma unroll 4
        for (int k = 0; k < DDIM; ++k) {
            ull ax[8], bv[4];
            #pragma unroll
            for (int q = 0; q < 4; ++q)
                bv[q] = *(const ull*)(bxb + k * SX + 32 * q);
            #pragma unroll
            for (int p = 0; p < 8; ++p) {
                float av = axb[k * SX + 16 * p];
                asm("mov.b64 %0, {%1, %1};" : "=l"(ax[p]) : "f"(av));
            }
            #pragma unroll
            for (int p = 0; p < 8; ++p)
                #pragma unroll
                for (int q = 0; q < 4; ++q)
                    asm("fma.rn.f32x2 %0, %1, %2, %0;"
                        : "+l"(acc[p][q]) : "l"(ax[p]), "l"(bv[q]));
        }

        // Chunk epilogue: acc.lo = code 2j, acc.hi = code 2j+1 (j = tx+16q).
        // lo evaluated before hi, q and c0 ascend; strict > keeps lowest index.
        #pragma unroll
        for (int q = 0; q < 4; ++q) {
            int j = tx + 16 * q;
            float hn0 = shn[2 * j], hn1 = shn[2 * j + 1];
            int cg = c0 + 2 * j;
            #pragma unroll
            for (int p = 0; p < 8; ++p) {
                float lo, hi;
                asm("mov.b64 {%0, %1}, %2;" : "=f"(lo), "=f"(hi) : "l"(acc[p][q]));
                float v0 = lo - hn0;
                float v1 = hi - hn1;
                if (v0 > bestv[p]) { bestv[p] = v0; besti[p] = cg; }
                if (v1 > bestv[p]) { bestv[p] = v1; besti[p] = cg + 1; }
            }
        }
    }

    // Reduce across the 16 code columns (lane = (ty&1)*16 + tx -> masks stay in group)
    #pragma unroll
    for (int p = 0; p < 8; ++p) {
        float v = bestv[p]; int ix = besti[p];
        #pragma unroll
        for (int m = 8; m >= 1; m >>= 1) {
            float ov = __shfl_xor_sync(0xffffffffu, v,  m);
            int   oi = __shfl_xor_sync(0xffffffffu, ix, m);
            if (ov > v || (ov == v && oi < ix)) { v = ov; ix = oi; }
        }
        if (tx == 0) sidx[ty + 16 * p] = ix;
    }
    __syncthreads();

    // Fused gather: out[b][d][s0+t] = cb[idx[t]][d]; coalesced writes, L2-hot reads.
    for (int e = tid; e < TM * DDIM; e += 256) {
        int d = e >> 7, t = e & 127;
        out[((long long)b * DDIM + d) * HW + s0 + t] = cb[sidx[t] * DDIM + d];
    }
    if (out_size > TOKENS * DDIM && tid < TM)
        out[TOKENS * DDIM + n0 + tid] = (float)sidx[tid];
}

#define SMEM_BYTES ((2 * DDIM * SX + TN) * 4 + TM * 4)

extern "C" void kernel_launch(void* const* d_in, const int* in_sizes, int n_in,
                              void* d_out, int out_size) {
    const float* inp = (const float*)d_in[0];   // (16, 64, 64, 64) f32
    const float* cb  = (const float*)d_in[1];   // (1024, 64) f32
    float* out = (float*)d_out;

    cudaFuncSetAttribute(vq_main, cudaFuncAttributeMaxDynamicSharedMemorySize,
                         SMEM_BYTES);

    vq_norms<<<KCODES * 32 / 256, 256>>>(cb);
    vq_main<<<TOKENS / TM, 256, SMEM_BYTES>>>(inp, cb, out, out_size);
}